// round 17
// baseline (speedup 1.0000x reference)
#include <cuda_runtime.h>
#include <cuda_bf16.h>
#include <cstdint>

#define M_TOT   8192
#define K_IN    4096
#define RANK    256
#define N_OUT   4096
#define VERA_SCALE (32.0f / 256.0f)

// pre-split bf16 hi/lo planes (packed 2 elems per uint32, row-major)
__device__ uint32_t g_Ahi[(size_t)RANK * K_IN / 2];
__device__ uint32_t g_Alo[(size_t)RANK * K_IN / 2];
__device__ uint32_t g_Bhi[(size_t)N_OUT * RANK / 2];
__device__ uint32_t g_Blo[(size_t)N_OUT * RANK / 2];
// split intermediate t = (x @ A^T) * d_A
__device__ uint32_t g_thi[(size_t)M_TOT * RANK / 2];
__device__ uint32_t g_tlo[(size_t)M_TOT * RANK / 2];

// ------------- helpers -------------
__device__ __forceinline__ uint32_t smem_u32(const void* p) {
    uint32_t a;
    asm("{ .reg .u64 t; cvta.to.shared.u64 t, %1; cvt.u32.u64 %0, t; }" : "=r"(a) : "l"(p));
    return a;
}
__device__ __forceinline__ void ldsm4(uint32_t r[4], uint32_t addr) {
    asm volatile("ldmatrix.sync.aligned.m8n8.x4.shared.b16 {%0,%1,%2,%3}, [%4];"
                 : "=r"(r[0]), "=r"(r[1]), "=r"(r[2]), "=r"(r[3]) : "r"(addr));
}
__device__ __forceinline__ void mma_bf16(float c[4], const uint32_t a[4],
                                         uint32_t b0, uint32_t b1) {
    asm volatile(
        "mma.sync.aligned.m16n8k16.row.col.f32.bf16.bf16.f32 "
        "{%0,%1,%2,%3}, {%4,%5,%6,%7}, {%8,%9}, {%0,%1,%2,%3};"
        : "+f"(c[0]), "+f"(c[1]), "+f"(c[2]), "+f"(c[3])
        : "r"(a[0]), "r"(a[1]), "r"(a[2]), "r"(a[3]), "r"(b0), "r"(b1));
}
__device__ __forceinline__ uint32_t sw128(uint32_t b) {
    return b ^ ((b >> 3) & 0x70);
}
__device__ __forceinline__ void split2(float a, float b, uint32_t& hi, uint32_t& lo) {
    uint32_t ua = __float_as_uint(a), ub = __float_as_uint(b);
    hi = __byte_perm(ua, ub, 0x7632);
    float fa = __uint_as_float(ua & 0xFFFF0000u);
    float fb = __uint_as_float(ub & 0xFFFF0000u);
    float la = a - fa, lb = b - fb;
    asm("cvt.rn.bf16x2.f32 %0, %1, %2;" : "=r"(lo) : "f"(lb), "f"(la));
}
__device__ __forceinline__ void cpa16(uint32_t dst, const void* src) {
    asm volatile("cp.async.cg.shared.global [%0], [%1], 16;" :: "r"(dst), "l"(src));
}
#define CP_COMMIT() asm volatile("cp.async.commit_group;" ::: "memory")
#define CP_WAIT0()  asm volatile("cp.async.wait_group 0;" ::: "memory")

// one-shot pre-split: fp32 matrix -> planar packed-bf16 hi/lo (A and B only)
__global__ void split_kernel(const float4* __restrict__ in, uint32_t* __restrict__ hi,
                             uint32_t* __restrict__ lo, int n4) {
    int i = blockIdx.x * blockDim.x + threadIdx.x;
    if (i < n4) {
        float4 v = in[i];
        uint32_t h0, l0, h1, l1;
        split2(v.x, v.y, h0, l0);
        split2(v.z, v.w, h1, l1);
        hi[2 * i] = h0; hi[2 * i + 1] = h1;
        lo[2 * i] = l0; lo[2 * i + 1] = l1;
    }
}

// ============ GEMM1: t = (x @ A^T) * d_A, direct emission (N-split) ============
// CTA 128(m) x 128(n), grid (64 m-tiles, 2 n-halves) = 128 CTAs. K=4096 in 64
// chunks of 64. 256 threads = 8 warps (2m x 4n), warp tile 64x32 (MMA:LDSM = 4).
// X: fp32, interleaved register-path producer. A: pre-split bf16 via cp.async.
// Epilogue folds d_A and writes split hi/lo t directly.
__global__ __launch_bounds__(256, 1)
void vera_g1(const float* __restrict__ X,
             const uint32_t* __restrict__ Ahi_, const uint32_t* __restrict__ Alo_,
             const float* __restrict__ dA,
             uint32_t* __restrict__ Thi, uint32_t* __restrict__ Tlo)
{
    extern __shared__ char smem[];
    constexpr int XP = 16384;                 // X bf16 plane (128 rows x 128B)
    constexpr int APLANE = 16384;             // A bf16 plane (128 rows x 128B)
    constexpr int AOFF = 2 * XP;              // 32768
    constexpr int STAGE = 2 * XP + 2 * APLANE;  // 65536
    constexpr int NC = 64;
    float* cs = reinterpret_cast<float*>(smem + 2 * STAGE);
    const uint32_t sb = smem_u32(smem);

    const int tid = threadIdx.x, wid = tid >> 5, lid = tid & 31;
    const int bm = blockIdx.x * 128;
    const int bn = blockIdx.y * 128;          // n-half of RANK
    const int Ku2 = K_IN / 2;

    if (tid < 128) cs[tid] = dA[bn + tid];

    // consumer addressing: warp tile 64(m) x 32(n)
    const int warp_m = wid & 1, warp_n = wid >> 1;
    const int rowA = warp_m * 64 + (lid & 15);
    const uint32_t kbA = (uint32_t)((lid >> 4) * 16);
    const uint32_t xA  = (uint32_t)((rowA & 7) << 4);
    uint32_t pA[4];
    #pragma unroll
    for (int mi = 0; mi < 4; ++mi) pA[mi] = (uint32_t)((rowA + mi * 16) * 128);
    const int rowB = warp_n * 32 + ((lid >> 4) * 8 + (lid & 7));
    const uint32_t pB0 = (uint32_t)(rowB * 128);
    const uint32_t kbB = (uint32_t)(((lid >> 3) & 1) * 16);
    const uint32_t xB  = (uint32_t)((rowB & 7) << 4);

    // X producer mapping: per s-step 2 float4/thread
    const float* Xg = X + (size_t)bm * K_IN;

    // A fill mapping: row = tid>>1, granule block (tid&1)*4
    const int frow = tid >> 1, fgb = (tid & 1) * 4;

    float acc[4][4][4];
    #pragma unroll
    for (int i = 0; i < 4; ++i)
        #pragma unroll
        for (int j = 0; j < 4; ++j)
            #pragma unroll
            for (int q = 0; q < 4; ++q) acc[i][j][q] = 0.0f;

    auto fillA = [&](uint32_t dstb, int ch) {
        const int col = ch * 32 + fgb * 4;
        #pragma unroll
        for (int j = 0; j < 4; ++j) {
            uint32_t off = sw128((uint32_t)(frow * 128 + (fgb + j) * 16));
            cpa16(dstb + AOFF + off,
                  Ahi_ + (size_t)(bn + frow) * Ku2 + col + j * 4);
            cpa16(dstb + AOFF + APLANE + off,
                  Alo_ + (size_t)(bn + frow) * Ku2 + col + j * 4);
        }
    };

    // prologue: stage 0
    fillA(sb, 0);
    CP_COMMIT();
    #pragma unroll
    for (int it = 0; it < 8; ++it) {
        int idx = tid + it * 256;
        int row = idx >> 4, c4 = (idx & 15) << 2;
        float4 v = *reinterpret_cast<const float4*>(Xg + (size_t)row * K_IN + c4);
        uint32_t h0, l0, h1, l1;
        split2(v.x, v.y, h0, l0);
        split2(v.z, v.w, h1, l1);
        uint32_t off = sw128((uint32_t)(row * 128 + c4 * 2));
        *reinterpret_cast<uint2*>(smem + off)      = make_uint2(h0, h1);
        *reinterpret_cast<uint2*>(smem + XP + off) = make_uint2(l0, l1);
    }
    CP_WAIT0();
    __syncthreads();

    for (int ch = 0; ch < NC; ++ch) {
        const uint32_t base = sb + (uint32_t)((ch & 1) * STAGE);
        const uint32_t dstb = sb + (uint32_t)(((ch & 1) ^ 1) * STAGE);
        char* dstc = smem + ((ch & 1) ^ 1) * STAGE;
        const bool more = (ch + 1 < NC);
        const float* Xn = Xg + (ch + 1) * 64;

        if (more) { fillA(dstb, ch + 1); CP_COMMIT(); }

        #pragma unroll
        for (int s = 0; s < 4; ++s) {
            // issue next-chunk X LDGs (2 float4), consumed after MMA block
            float4 xv0, xv1;
            int row0 = 0, row1 = 0, c40 = 0, c41 = 0;
            if (more) {
                int idx0 = tid + (2 * s) * 256;
                int idx1 = tid + (2 * s + 1) * 256;
                row0 = idx0 >> 4; c40 = (idx0 & 15) << 2;
                row1 = idx1 >> 4; c41 = (idx1 & 15) << 2;
                xv0 = *reinterpret_cast<const float4*>(Xn + (size_t)row0 * K_IN + c40);
                xv1 = *reinterpret_cast<const float4*>(Xn + (size_t)row1 * K_IN + c41);
            }

            const uint32_t aoff = ((uint32_t)(s * 32) + kbA) ^ xA;
            const uint32_t boff = ((uint32_t)(s * 32) + kbB) ^ xB;
            uint32_t ah[4][4], al[4][4];
            #pragma unroll
            for (int mi = 0; mi < 4; ++mi) {
                ldsm4(ah[mi], base + pA[mi] + aoff);
                ldsm4(al[mi], base + XP + pA[mi] + aoff);
            }
            #pragma unroll
            for (int g = 0; g < 2; ++g) {
                uint32_t bh[4], bl[4];
                const uint32_t nb = base + AOFF + pB0 + boff + (uint32_t)(g * 2048);
                ldsm4(bh, nb);
                ldsm4(bl, nb + APLANE);
                #pragma unroll
                for (int mi = 0; mi < 4; ++mi) {
                    mma_bf16(acc[mi][2 * g],     ah[mi], bh[0], bh[1]);
                    mma_bf16(acc[mi][2 * g + 1], ah[mi], bh[2], bh[3]);
                }
                #pragma unroll
                for (int mi = 0; mi < 4; ++mi) {
                    mma_bf16(acc[mi][2 * g],     ah[mi], bl[0], bl[1]);
                    mma_bf16(acc[mi][2 * g + 1], ah[mi], bl[2], bl[3]);
                }
                #pragma unroll
                for (int mi = 0; mi < 4; ++mi) {
                    mma_bf16(acc[mi][2 * g],     al[mi], bh[0], bh[1]);
                    mma_bf16(acc[mi][2 * g + 1], al[mi], bh[2], bh[3]);
                }
            }

            if (more) {
                uint32_t h0, l0, h1, l1;
                split2(xv0.x, xv0.y, h0, l0);
                split2(xv0.z, xv0.w, h1, l1);
                uint32_t off = sw128((uint32_t)(row0 * 128 + c40 * 2));
                *reinterpret_cast<uint2*>(dstc + off)      = make_uint2(h0, h1);
                *reinterpret_cast<uint2*>(dstc + XP + off) = make_uint2(l0, l1);
                split2(xv1.x, xv1.y, h0, l0);
                split2(xv1.z, xv1.w, h1, l1);
                off = sw128((uint32_t)(row1 * 128 + c41 * 2));
                *reinterpret_cast<uint2*>(dstc + off)      = make_uint2(h0, h1);
                *reinterpret_cast<uint2*>(dstc + XP + off) = make_uint2(l0, l1);
            }
        }
        CP_WAIT0();
        __syncthreads();
    }

    // epilogue: fold d_A, emit split hi/lo t
    const int mrow0 = bm + warp_m * 64 + (lid >> 2);
    const int nc0   = warp_n * 32 + (lid & 3) * 2;
    #pragma unroll
    for (int mi = 0; mi < 4; ++mi) {
        #pragma unroll
        for (int nj = 0; nj < 4; ++nj) {
            const int n = nc0 + nj * 8;
            const float s0 = cs[n], s1 = cs[n + 1];
            const int m0 = mrow0 + mi * 16;
            const size_t o0 = (size_t)m0 * (RANK / 2) + ((bn + n) >> 1);
            const size_t o1 = (size_t)(m0 + 8) * (RANK / 2) + ((bn + n) >> 1);
            uint32_t h, l;
            split2(acc[mi][nj][0] * s0, acc[mi][nj][1] * s1, h, l);
            Thi[o0] = h; Tlo[o0] = l;
            split2(acc[mi][nj][2] * s0, acc[mi][nj][3] * s1, h, l);
            Thi[o1] = h; Tlo[o1] = l;
        }
    }
}

// ============ GEMM2 (verbatim R11/R16 engine, measured 130us) ============
__global__ __launch_bounds__(512, 1)
void vera_g2(const uint32_t* __restrict__ Thi_, const uint32_t* __restrict__ Tlo_,
             const uint32_t* __restrict__ Bhi_, const uint32_t* __restrict__ Blo_,
             const float* __restrict__ dB, float* __restrict__ Out)
{
    extern __shared__ char smem[];
    constexpr int AP = 16384, BP = 32768;
    constexpr int STAGE = 2 * AP + 2 * BP;   // 96KB
    float* cs = reinterpret_cast<float*>(smem + 2 * STAGE);
    const uint32_t sb = smem_u32(smem);

    const int tid = threadIdx.x, wid = tid >> 5, lid = tid & 31;
    const int warp_m = wid & 3, warp_n = wid >> 2;
    const int bm = blockIdx.x * 128, bn = blockIdx.y * 256;
    const int Ku2 = RANK / 2;

    if (tid < 256) cs[tid] = dB[bn + tid] * VERA_SCALE;

    const int rowA = warp_m * 32 + (lid & 15);
    const uint32_t pA0 = (uint32_t)(rowA * 128), pA1 = pA0 + 2048;
    const uint32_t kbA = (uint32_t)((lid >> 4) * 16);
    const uint32_t xA  = (uint32_t)((rowA & 7) << 4);
    const int rowB = warp_n * 64 + ((lid >> 4) * 8 + (lid & 7));
    const uint32_t pB0 = (uint32_t)(rowB * 128);
    const uint32_t kbB = (uint32_t)(((lid >> 3) & 1) * 16);
    const uint32_t xB  = (uint32_t)((rowB & 7) << 4);

    const int frow = tid >> 3, fc16 = tid & 7;

    float acc[2][8][4];
    #pragma unroll
    for (int i = 0; i < 2; ++i)
        #pragma unroll
        for (int j = 0; j < 8; ++j)
            #pragma unroll
            for (int q = 0; q < 4; ++q) acc[i][j][q] = 0.0f;

    auto fill = [&](uint32_t dstb, int c) {
        const int col = c * 32 + fc16 * 4;
        #pragma unroll
        for (int j = 0; j < 2; ++j) {
            int row = frow + j * 64;
            uint32_t off = sw128((uint32_t)(row * 128 + fc16 * 16));
            cpa16(dstb + off,      Thi_ + (size_t)(bm + row) * Ku2 + col);
            cpa16(dstb + AP + off, Tlo_ + (size_t)(bm + row) * Ku2 + col);
        }
        #pragma unroll
        for (int j = 0; j < 4; ++j) {
            int row = frow + j * 64;
            uint32_t off = sw128((uint32_t)(row * 128 + fc16 * 16));
            cpa16(dstb + 2 * AP + off,      Bhi_ + (size_t)(bn + row) * Ku2 + col);
            cpa16(dstb + 2 * AP + BP + off, Blo_ + (size_t)(bn + row) * Ku2 + col);
        }
    };

    fill(sb, 0);
    CP_COMMIT(); CP_WAIT0();
    __syncthreads();

    #pragma unroll
    for (int ch = 0; ch < 4; ++ch) {
        const uint32_t base = sb + (uint32_t)((ch & 1) * STAGE);
        if (ch < 3) { fill(sb + (uint32_t)(((ch & 1) ^ 1) * STAGE), ch + 1); CP_COMMIT(); }

        #pragma unroll
        for (int s = 0; s < 4; ++s) {
            const uint32_t aoff = ((uint32_t)(s * 32) + kbA) ^ xA;
            const uint32_t boff = ((uint32_t)(s * 32) + kbB) ^ xB;
            uint32_t ah[2][4], al[2][4];
            ldsm4(ah[0], base + pA0 + aoff);
            ldsm4(ah[1], base + pA1 + aoff);
            ldsm4(al[0], base + AP + pA0 + aoff);
            ldsm4(al[1], base + AP + pA1 + aoff);
            #pragma unroll
            for (int g = 0; g < 2; ++g) {
                uint32_t bh[2][4], bl[2][4];
                const uint32_t nb = base + 2 * AP + pB0 + boff + (uint32_t)(g * 4096);
                ldsm4(bh[0], nb);
                ldsm4(bh[1], nb + 2048);
                ldsm4(bl[0], nb + BP);
                ldsm4(bl[1], nb + BP + 2048);
                #pragma unroll
                for (int np = 0; np < 2; ++np)
                    #pragma unroll
                    for (int mi = 0; mi < 2; ++mi) {
                        const int j = (g * 2 + np) * 2;
                        mma_bf16(acc[mi][j],     ah[mi], bh[np][0], bh[np][1]);
                        mma_bf16(acc[mi][j + 1], ah[mi], bh[np][2], bh[np][3]);
                    }
                #pragma unroll
                for (int np = 0; np < 2; ++np)
                    #pragma unroll
                    for (int mi = 0; mi < 2; ++mi) {
                        const int j = (g * 2 + np) * 2;
                        mma_bf16(acc[mi][j],     ah[mi], bl[np][0], bl[np][1]);
                        mma_bf16(acc[mi][j + 1], ah[mi], bl[np][2], bl[np][3]);
                    }
                #pragma unroll
                for (int np = 0; np < 2; ++np)
                    #pragma unroll
                    for (int mi = 0; mi < 2; ++mi) {
                        const int j = (g * 2 + np) * 2;
                        mma_bf16(acc[mi][j],     al[mi], bh[np][0], bh[np][1]);
                        mma_bf16(acc[mi][j + 1], al[mi], bh[np][2], bh[np][3]);
                    }
            }
        }
        CP_WAIT0();
        __syncthreads();
    }

    const int mrow0 = bm + warp_m * 32 + (lid >> 2);
    const int nc0   = warp_n * 64 + (lid & 3) * 2;
    #pragma unroll
    for (int mi = 0; mi < 2; ++mi) {
        #pragma unroll
        for (int nj = 0; nj < 8; ++nj) {
            const int n = nc0 + nj * 8;
            const float s0 = cs[n], s1 = cs[n + 1];
            float2 v0, v1;
            v0.x = acc[mi][nj][0] * s0; v0.y = acc[mi][nj][1] * s1;
            v1.x = acc[mi][nj][2] * s0; v1.y = acc[mi][nj][3] * s1;
            const int m0 = mrow0 + mi * 16;
            *reinterpret_cast<float2*>(Out + (size_t)m0 * N_OUT + bn + n) = v0;
            *reinterpret_cast<float2*>(Out + (size_t)(m0 + 8) * N_OUT + bn + n) = v1;
        }
    }
}

extern "C" void kernel_launch(void* const* d_in, const int* in_sizes, int n_in,
                              void* d_out, int out_size)
{
    const float* x   = (const float*)d_in[0];  // [8192][4096]
    const float* A   = (const float*)d_in[1];  // [256][4096]
    const float* B   = (const float*)d_in[2];  // [4096][256]
    const float* d_A = (const float*)d_in[3];  // [256]
    const float* d_B = (const float*)d_in[4];  // [4096]
    float* out = (float*)d_out;                // [8192][4096]

    uint32_t *Ahi, *Alo, *Bhi, *Blo, *thi, *tlo;
    cudaGetSymbolAddress((void**)&Ahi, g_Ahi);
    cudaGetSymbolAddress((void**)&Alo, g_Alo);
    cudaGetSymbolAddress((void**)&Bhi, g_Bhi);
    cudaGetSymbolAddress((void**)&Blo, g_Blo);
    cudaGetSymbolAddress((void**)&thi, g_thi);
    cudaGetSymbolAddress((void**)&tlo, g_tlo);

    constexpr int SMEM1 = 2 * 65536 + 512;                    // 131584
    constexpr int SMEM2 = 2 * (2 * 16384 + 2 * 32768) + 1024; // 197632
    cudaFuncSetAttribute(vera_g1, cudaFuncAttributeMaxDynamicSharedMemorySize, SMEM1);
    cudaFuncSetAttribute(vera_g2, cudaFuncAttributeMaxDynamicSharedMemorySize, SMEM2);

    // pre-split A and B (small; X handled in-kernel by vera_g1)
    {
        int n4 = RANK * K_IN / 4;
        split_kernel<<<n4 / 256, 256>>>((const float4*)A, Ahi, Alo, n4);
        int n4b = N_OUT * RANK / 4;
        split_kernel<<<n4b / 256, 256>>>((const float4*)B, Bhi, Blo, n4b);
    }
    // GEMM1 (N-split, direct t emission with d_A folded)
    {
        dim3 grid(M_TOT / 128, RANK / 128);   // 64 x 2 = 128 CTAs
        vera_g1<<<grid, 256, SMEM1>>>(x, Ahi, Alo, d_A, thi, tlo);
    }
    // GEMM2
    {
        dim3 grid(M_TOT / 128, N_OUT / 256);  // 64 x 16
        vera_g2<<<grid, 512, SMEM2>>>(thi, tlo, Bhi, Blo, d_B, out);
    }
}